// round 9
// baseline (speedup 1.0000x reference)
#include <cuda_runtime.h>

// MatchAttention fused forward, fixed shape:
// B=2, H=W=64, N=4096, C=256, heads=8, Ch=32, r=3 -> K=49, scale=1, l1_norm.
#define HH   64
#define WW   64
#define CC   256
#define NHD  8
#define CH   32
#define RR   3
#define KWIN 49
#define NPIX (HH * WW)

// One warp = 4 heads of one pixel (8 lanes/head, 4 channels/lane).
// Slots in 6 groups of 8 + remainder. Two groups (jj, jj+3) are processed as
// independent interleaved streams: their 3-round transposed butterflies,
// exps and v-accumulations alternate so each stream's SHFL/MUFU latency is
// hidden by the other stream's issue slots.
// Streaming softmax with fixed reference (sim <= 0 always; d ~ 36+/-5 so
// exp(-d) is far above fp32 underflow); final 1/sum rescale == reference.
__global__ __launch_bounds__(256, 4)
void match_attn_kernel(const float* __restrict__ moff,   // [B,N,h,2]
                       const float* __restrict__ qp,     // [B,N,C]
                       const float* __restrict__ kp,     // [B,N,C]
                       const float* __restrict__ vp,     // [B,N,C]
                       float* __restrict__ out,          // [B,N,C]
                       float* __restrict__ attn_out)     // [B,N,h,K]
{
    const int warpGlobal = (blockIdx.x * blockDim.x + threadIdx.x) >> 5;
    const int lane = threadIdx.x & 31;
    const int lig  = lane & 7;    // lane within 8-lane head group
    const int grp  = lane >> 3;   // head-in-half

    const int p = warpGlobal >> 1;               // global pixel (incl batch)
    const int g = (warpGlobal & 1) * 4 + grp;    // head id

    const int n    = p & (NPIX - 1);
    const int base = p - n;                      // b*N
    const int y    = n / WW;
    const int x    = n & (WW - 1);

    // rounded per-head window center (rintf == jnp.round, half-to-even)
    const float2 off2 = *(const float2*)&moff[(size_t)(p * NHD + g) * 2];
    const int cy = y + (int)rintf(off2.x);
    const int cx = x + (int)rintf(off2.y);

    const int chBase = g * CH + lig * 4;

    // clamped row/col element-offsets; chBase folded into the row term
    int pyW[7], pxc[7];
#pragma unroll
    for (int i = 0; i < 7; i++) {
        const int py = min(max(cy + i - RR, 0), HH - 1);
        const int px = min(max(cx + i - RR, 0), WW - 1);
        pyW[i] = (base + py * WW) * CC + chBase;
        pxc[i] = px * CC;
    }

    const float4 q4 = *(const float4*)(qp + (size_t)p * CC + chBase);

    const bool b0 = (lig & 1) != 0;
    const bool b1 = (lig & 2) != 0;
    const bool b2 = (lig & 4) != 0;
    const int  gbase = lane & 24;   // first lane of this head group

    float w_ownA[3], w_ownB[3];
    float s = 0.f;
    float4 acc = make_float4(0.f, 0.f, 0.f, 0.f);

#pragma unroll
    for (int jj = 0; jj < 3; jj++) {
        const int baseA = jj * 8;        // stream A: slots baseA..baseA+7
        const int baseB = jj * 8 + 24;   // stream B: slots baseB..baseB+7

        // ---- k gathers + partial L1 distances, both streams -----------------
        float pdA[8], pdB[8];
#pragma unroll
        for (int t = 0; t < 8; t++) {
            const int ka = baseA + t;
            const float4 k4 = *(const float4*)(kp + pyW[ka / 7] + pxc[ka % 7]);
            pdA[t] = fabsf(q4.x - k4.x) + fabsf(q4.y - k4.y)
                   + fabsf(q4.z - k4.z) + fabsf(q4.w - k4.w);
        }
#pragma unroll
        for (int t = 0; t < 8; t++) {
            const int kb = baseB + t;
            const float4 k4 = *(const float4*)(kp + pyW[kb / 7] + pxc[kb % 7]);
            pdB[t] = fabsf(q4.x - k4.x) + fabsf(q4.y - k4.y)
                   + fabsf(q4.z - k4.z) + fabsf(q4.w - k4.w);
        }

        // ---- interleaved transposed butterflies (A and B alternate) ---------
        float r4A[4], r4B[4];
#pragma unroll
        for (int t = 0; t < 4; t++) {
            const float keepA = b0 ? pdA[2 * t + 1] : pdA[2 * t];
            const float sendA = b0 ? pdA[2 * t]     : pdA[2 * t + 1];
            r4A[t] = keepA + __shfl_xor_sync(0xffffffffu, sendA, 1);
            const float keepB = b0 ? pdB[2 * t + 1] : pdB[2 * t];
            const float sendB = b0 ? pdB[2 * t]     : pdB[2 * t + 1];
            r4B[t] = keepB + __shfl_xor_sync(0xffffffffu, sendB, 1);
        }
        float r2A[2], r2B[2];
#pragma unroll
        for (int t = 0; t < 2; t++) {
            const float keepA = b1 ? r4A[2 * t + 1] : r4A[2 * t];
            const float sendA = b1 ? r4A[2 * t]     : r4A[2 * t + 1];
            r2A[t] = keepA + __shfl_xor_sync(0xffffffffu, sendA, 2);
            const float keepB = b1 ? r4B[2 * t + 1] : r4B[2 * t];
            const float sendB = b1 ? r4B[2 * t]     : r4B[2 * t + 1];
            r2B[t] = keepB + __shfl_xor_sync(0xffffffffu, sendB, 2);
        }
        const float keepA = b2 ? r2A[1] : r2A[0];
        const float sendA = b2 ? r2A[0] : r2A[1];
        const float dA = keepA + __shfl_xor_sync(0xffffffffu, sendA, 4);
        const float keepB = b2 ? r2B[1] : r2B[0];
        const float sendB = b2 ? r2B[0] : r2B[1];
        const float dB = keepB + __shfl_xor_sync(0xffffffffu, sendB, 4);

        const float wA = __expf(-dA);
        const float wB = __expf(-dB);
        s += wA + wB;
        w_ownA[jj] = wA;
        w_ownB[jj] = wB;

        // ---- v accumulation, streams interleaved ----------------------------
#pragma unroll
        for (int t = 0; t < 8; t++) {
            const int ka = baseA + t;
            const float wtA = __shfl_sync(0xffffffffu, wA, gbase | t);
            const float4 vA = *(const float4*)(vp + pyW[ka / 7] + pxc[ka % 7]);
            acc.x = fmaf(wtA, vA.x, acc.x);
            acc.y = fmaf(wtA, vA.y, acc.y);
            acc.z = fmaf(wtA, vA.z, acc.z);
            acc.w = fmaf(wtA, vA.w, acc.w);
            const int kb = baseB + t;
            const float wtB = __shfl_sync(0xffffffffu, wB, gbase | t);
            const float4 vB = *(const float4*)(vp + pyW[kb / 7] + pxc[kb % 7]);
            acc.x = fmaf(wtB, vB.x, acc.x);
            acc.y = fmaf(wtB, vB.y, acc.y);
            acc.z = fmaf(wtB, vB.z, acc.z);
            acc.w = fmaf(wtB, vB.w, acc.w);
        }
    }

    // ---- remainder slot 48 (row 6, col 6) ------------------------------------
    float w48;
    {
        const int off48 = pyW[6] + pxc[6];
        const float4 k4 = *(const float4*)(kp + off48);
        float d = fabsf(q4.x - k4.x) + fabsf(q4.y - k4.y)
                + fabsf(q4.z - k4.z) + fabsf(q4.w - k4.w);
        d += __shfl_xor_sync(0xffffffffu, d, 1);
        d += __shfl_xor_sync(0xffffffffu, d, 2);
        d += __shfl_xor_sync(0xffffffffu, d, 4);
        w48 = __expf(-d);                        // full weight on all 8 lanes
        const float4 v4 = *(const float4*)(vp + off48);
        acc.x = fmaf(w48, v4.x, acc.x);
        acc.y = fmaf(w48, v4.y, acc.y);
        acc.z = fmaf(w48, v4.z, acc.z);
        acc.w = fmaf(w48, v4.w, acc.w);
    }

    // ---- normalization --------------------------------------------------------
    // per-lane s covers its 6 owned slots; reduce over the head group, add 48
    s += __shfl_xor_sync(0xffffffffu, s, 1);
    s += __shfl_xor_sync(0xffffffffu, s, 2);
    s += __shfl_xor_sync(0xffffffffu, s, 4);
    s += w48;
    const float inv = 1.f / s;

    float* aout = attn_out + (size_t)(p * NHD + g) * KWIN;
#pragma unroll
    for (int jj = 0; jj < 3; jj++) {
        aout[jj * 8 + lig]      = w_ownA[jj] * inv;
        aout[jj * 8 + 24 + lig] = w_ownB[jj] * inv;
    }
    if (lig == 0) aout[48] = w48 * inv;

    acc.x *= inv; acc.y *= inv; acc.z *= inv; acc.w *= inv;
    *(float4*)(out + (size_t)p * CC + chBase) = acc;
}

extern "C" void kernel_launch(void* const* d_in, const int* in_sizes, int n_in,
                              void* d_out, int out_size) {
    const float* moff = (const float*)d_in[0];   // [B,N,h,2]
    const float* q    = (const float*)d_in[1];   // [B,N,C]
    const float* k    = (const float*)d_in[2];
    const float* v    = (const float*)d_in[3];

    float* out = (float*)d_out;                  // output [B,N,C] first...
    const int qElems = in_sizes[1];              // B*N*C
    float* attn_out = out + qElems;              // ...then attn_out [B,N,h,K]

    const int items = in_sizes[0] / 2;           // B*N*h
    const int totalWarps = items / 4;            // 4 heads per warp
    const int threads = 256;
    const int blocks = (totalWarps * 32) / threads;   // 2048

    match_attn_kernel<<<blocks, threads>>>(moff, q, k, v, out, attn_out);
}

// round 10
// speedup vs baseline: 1.0679x; 1.0679x over previous
#include <cuda_runtime.h>

// MatchAttention fused forward, fixed shape:
// B=2, H=W=64, N=4096, C=256, heads=8, Ch=32, r=3 -> K=49, scale=1, l1_norm.
#define HH   64
#define WW   64
#define CC   256
#define NHD  8
#define CH   32
#define RR   3
#define KWIN 49
#define NPIX (HH * WW)

// packed f32x2 helpers (sm_10x). Used ONLY where no unpack is needed:
// v-vectors come straight from LDG.128 register quads, acc stays packed.
__device__ __forceinline__ void fma2(unsigned long long& acc,
                                     unsigned long long v,
                                     unsigned long long w2) {
    asm("fma.rn.f32x2 %0, %1, %2, %0;" : "+l"(acc) : "l"(v), "l"(w2));
}
__device__ __forceinline__ unsigned long long pack2(float a, float b) {
    unsigned long long r;
    asm("mov.b64 %0, {%1, %2};" : "=l"(r) : "f"(a), "f"(b));
    return r;
}
__device__ __forceinline__ void mul2(unsigned long long& a, unsigned long long b) {
    asm("mul.rn.f32x2 %0, %0, %1;" : "+l"(a) : "l"(b));
}

// One warp = 4 heads of one pixel (8 lanes/head, 4 channels/lane).
// Slots in 6 groups of 8 + 1 remainder; per group a transposed 3-round
// butterfly leaves lane `lig` holding the FULL L1 distance of slot 8j+lig,
// and only the owner lane runs exp. R10: the first 4 v-loads of each group
// are issued BEFORE the butterfly (latency hidden by the shfl rounds), and
// the v accumulation uses packed FFMA2 with no unpack anywhere.
// Streaming softmax with fixed reference (sim <= 0 always; d ~ 36+/-5 so
// exp(-d) is far above fp32 underflow); final 1/sum rescale == reference.
__global__ __launch_bounds__(256, 4)
void match_attn_kernel(const float* __restrict__ moff,   // [B,N,h,2]
                       const float* __restrict__ qp,     // [B,N,C]
                       const float* __restrict__ kp,     // [B,N,C]
                       const float* __restrict__ vp,     // [B,N,C]
                       float* __restrict__ out,          // [B,N,C]
                       float* __restrict__ attn_out)     // [B,N,h,K]
{
    const int warpGlobal = (blockIdx.x * blockDim.x + threadIdx.x) >> 5;
    const int lane = threadIdx.x & 31;
    const int lig  = lane & 7;    // lane within 8-lane head group
    const int grp  = lane >> 3;   // head-in-half

    const int p = warpGlobal >> 1;               // global pixel (incl batch)
    const int g = (warpGlobal & 1) * 4 + grp;    // head id

    const int n    = p & (NPIX - 1);
    const int base = p - n;                      // b*N
    const int y    = n / WW;
    const int x    = n & (WW - 1);

    // rounded per-head window center (rintf == jnp.round, half-to-even)
    const float2 off2 = *(const float2*)&moff[(size_t)(p * NHD + g) * 2];
    const int cy = y + (int)rintf(off2.x);
    const int cx = x + (int)rintf(off2.y);

    const int chBase = g * CH + lig * 4;

    // clamped row/col element-offsets; chBase folded into the row term
    int pyW[7], pxc[7];
#pragma unroll
    for (int i = 0; i < 7; i++) {
        const int py = min(max(cy + i - RR, 0), HH - 1);
        const int px = min(max(cx + i - RR, 0), WW - 1);
        pyW[i] = (base + py * WW) * CC + chBase;
        pxc[i] = px * CC;
    }

    const float4 q4 = *(const float4*)(qp + (size_t)p * CC + chBase);

    const bool b0 = (lig & 1) != 0;
    const bool b1 = (lig & 2) != 0;
    const bool b2 = (lig & 4) != 0;
    const int  gbase = lane & 24;   // first lane of this head group

    float w_own[6];
    float s = 0.f;
    unsigned long long acc0 = 0ull, acc1 = 0ull;   // 4 channels, packed f32x2

#pragma unroll
    for (int j = 0; j < 6; j++) {
        // ---- shared addresses for this group (k and v gathers) --------------
        int offs[8];
#pragma unroll
        for (int t = 0; t < 8; t++) {
            const int kk = j * 8 + t;
            offs[t] = pyW[kk / 7] + pxc[kk % 7];
        }

        // ---- 8 k-gathers + per-lane partial L1 distances ---------------------
        float pd[8];
#pragma unroll
        for (int t = 0; t < 8; t++) {
            const float4 k4 = *(const float4*)(kp + offs[t]);
            pd[t] = fabsf(q4.x - k4.x) + fabsf(q4.y - k4.y)
                  + fabsf(q4.z - k4.z) + fabsf(q4.w - k4.w);
        }

        // ---- stage first 4 v-loads; butterfly below hides their latency ------
        ulonglong2 vst[4];
#pragma unroll
        for (int t = 0; t < 4; t++)
            vst[t] = *(const ulonglong2*)(vp + offs[t]);

        // ---- transposed butterfly: lane lig ends with full d of slot 8j+lig --
        float r4[4];
#pragma unroll
        for (int t = 0; t < 4; t++) {
            const float keep = b0 ? pd[2 * t + 1] : pd[2 * t];
            const float send = b0 ? pd[2 * t]     : pd[2 * t + 1];
            r4[t] = keep + __shfl_xor_sync(0xffffffffu, send, 1);
        }
        float r2[2];
#pragma unroll
        for (int t = 0; t < 2; t++) {
            const float keep = b1 ? r4[2 * t + 1] : r4[2 * t];
            const float send = b1 ? r4[2 * t]     : r4[2 * t + 1];
            r2[t] = keep + __shfl_xor_sync(0xffffffffu, send, 2);
        }
        const float keep = b2 ? r2[1] : r2[0];
        const float send = b2 ? r2[0] : r2[1];
        const float d = keep + __shfl_xor_sync(0xffffffffu, send, 4);

        const float w = __expf(-d);   // weight of owned slot 8j+lig
        s += w;
        w_own[j] = w;

        // ---- v accumulation: staged slots 0-3 -------------------------------
#pragma unroll
        for (int t = 0; t < 4; t++) {
            const float wt = __shfl_sync(0xffffffffu, w, gbase | t);
            const unsigned long long w2v = pack2(wt, wt);
            fma2(acc0, vst[t].x, w2v);
            fma2(acc1, vst[t].y, w2v);
        }
        // ---- slots 4-7: load + accumulate (latency covered by slots 0-3) ----
#pragma unroll
        for (int t = 4; t < 8; t++) {
            const ulonglong2 v2 = *(const ulonglong2*)(vp + offs[t]);
            const float wt = __shfl_sync(0xffffffffu, w, gbase | t);
            const unsigned long long w2v = pack2(wt, wt);
            fma2(acc0, v2.x, w2v);
            fma2(acc1, v2.y, w2v);
        }
    }

    // ---- remainder slot 48 (row 6, col 6) ------------------------------------
    float w48;
    {
        const int off48 = pyW[6] + pxc[6];
        const float4 k4 = *(const float4*)(kp + off48);
        const ulonglong2 v2 = *(const ulonglong2*)(vp + off48);
        float d = fabsf(q4.x - k4.x) + fabsf(q4.y - k4.y)
                + fabsf(q4.z - k4.z) + fabsf(q4.w - k4.w);
        d += __shfl_xor_sync(0xffffffffu, d, 1);
        d += __shfl_xor_sync(0xffffffffu, d, 2);
        d += __shfl_xor_sync(0xffffffffu, d, 4);
        w48 = __expf(-d);                        // full weight on all 8 lanes
        const unsigned long long w2v = pack2(w48, w48);
        fma2(acc0, v2.x, w2v);
        fma2(acc1, v2.y, w2v);
    }

    // ---- normalization --------------------------------------------------------
    // per-lane s covers its 6 owned slots; reduce over the head group, add 48
    s += __shfl_xor_sync(0xffffffffu, s, 1);
    s += __shfl_xor_sync(0xffffffffu, s, 2);
    s += __shfl_xor_sync(0xffffffffu, s, 4);
    s += w48;
    const float inv = 1.f / s;

    float* aout = attn_out + (size_t)(p * NHD + g) * KWIN;
#pragma unroll
    for (int j = 0; j < 6; j++) aout[j * 8 + lig] = w_own[j] * inv;
    if (lig == 0) aout[48] = w48 * inv;

    const unsigned long long inv2 = pack2(inv, inv);
    mul2(acc0, inv2);
    mul2(acc1, inv2);
    *(ulonglong2*)(out + (size_t)p * CC + chBase) = make_ulonglong2(acc0, acc1);
}

extern "C" void kernel_launch(void* const* d_in, const int* in_sizes, int n_in,
                              void* d_out, int out_size) {
    const float* moff = (const float*)d_in[0];   // [B,N,h,2]
    const float* q    = (const float*)d_in[1];   // [B,N,C]
    const float* k    = (const float*)d_in[2];
    const float* v    = (const float*)d_in[3];

    float* out = (float*)d_out;                  // output [B,N,C] first...
    const int qElems = in_sizes[1];              // B*N*C
    float* attn_out = out + qElems;              // ...then attn_out [B,N,h,K]

    const int items = in_sizes[0] / 2;           // B*N*h
    const int totalWarps = items / 4;            // 4 heads per warp
    const int threads = 256;
    const int blocks = (totalWarps * 32) / threads;   // 2048

    match_attn_kernel<<<blocks, threads>>>(moff, q, k, v, out, attn_out);
}